// round 1
// baseline (speedup 1.0000x reference)
#include <cuda_runtime.h>
#include <math.h>

#define Nn   30000
#define Ee   480000
#define ET   510000   // Ee + Nn self loops
#define Bb   48
#define HD   256      // H*D
#define NH   4
#define NOUT 128
#define NIN  8
#define NL   10

// ---------------- device scratch (static, no allocs) ----------------
__device__ float4 d_H4[Nn * 64];     // H = X @ W        [N,256]
__device__ float4 d_OUT4[Nn * 64];   // layer output     [N,256]
__device__ float4 d_AS4[Nn];         // alpha_src        [N,4]
__device__ float4 d_AD4[Nn];         // alpha_dst        [N,4]
__device__ float4 d_W44[ET];         // per-edge exp weights [ET,4]
__device__ int    d_deg[Nn];
__device__ int    d_rowptr[Nn + 1];
__device__ int    d_cursor[Nn];
__device__ int    d_colsrc[ET];
__device__ int    d_colrow[ET];
__device__ float  d_G[Bb * 4 * HD];  // pooled [min|max|mean|sum]

#define d_Hf   ((float*)d_H4)
#define d_OUTf ((float*)d_OUT4)
#define d_ASf  ((float*)d_AS4)
#define d_ADf  ((float*)d_AD4)
#define d_W4f  ((float*)d_W44)

__device__ __forceinline__ float gelu_f(float x) {
    return 0.5f * x * (1.0f + erff(x * 0.70710678118654752f));
}

// ---------------- CSR build ----------------
__global__ void deg_init_kernel() {
    int i = blockIdx.x * blockDim.x + threadIdx.x;
    if (i < Nn) d_deg[i] = 1;   // self loop
}

__global__ void hist_kernel(const int* __restrict__ dst) {
    int i = blockIdx.x * blockDim.x + threadIdx.x;
    if (i < Ee) atomicAdd(&d_deg[dst[i]], 1);
}

__global__ void scan_kernel() {
    __shared__ int sh[1024];
    const int t = threadIdx.x;
    const int CH = (Nn + 1023) / 1024;   // 30
    int start = t * CH;
    int end   = min(start + CH, Nn);
    int s = 0;
    for (int i = start; i < end; i++) s += d_deg[i];
    sh[t] = s;
    __syncthreads();
    for (int off = 1; off < 1024; off <<= 1) {
        int v = (t >= off) ? sh[t - off] : 0;
        __syncthreads();
        sh[t] += v;
        __syncthreads();
    }
    int run = sh[t] - s;   // exclusive prefix
    for (int i = start; i < end; i++) {
        d_rowptr[i] = run;
        d_cursor[i] = run;
        run += d_deg[i];
    }
    if (t == 1023) d_rowptr[Nn] = sh[1023];
}

__global__ void scatter_kernel(const int* __restrict__ src,
                               const int* __restrict__ dst) {
    int i = blockIdx.x * blockDim.x + threadIdx.x;
    if (i >= ET) return;
    int s, d;
    if (i < Ee) { s = src[i]; d = dst[i]; }
    else        { s = d = i - Ee; }
    int pos = atomicAdd(&d_cursor[d], 1);
    d_colsrc[pos] = s;
    d_colrow[pos] = d;
}

// Sort each row's srcs ascending (odd-even transposition, warp/row) so the
// CSR is bitwise deterministic regardless of scatter atomic ordering.
__global__ void sort_rows_kernel() {
    int t   = blockIdx.x * blockDim.x + threadIdx.x;
    int wid = t >> 5, lane = t & 31;
    if (wid >= Nn) return;
    int s0 = d_rowptr[wid], s1 = d_rowptr[wid + 1];
    int n = s1 - s0;
    for (int p = 0; p < n; p++) {
        for (int i = (p & 1) + 2 * lane; i + 1 < n; i += 64) {
            int a = d_colsrc[s0 + i], b = d_colsrc[s0 + i + 1];
            if (a > b) { d_colsrc[s0 + i] = b; d_colsrc[s0 + i + 1] = a; }
        }
        __syncwarp();
    }
}

// ---------------- GEMM: d_H = (GELU?)A @ W   (A:[M,K], W:[K,256]) ----------------
template <bool GELU>
__global__ void __launch_bounds__(256)
gemm_kernel(const float* __restrict__ A, const float* __restrict__ W,
            int M, int K) {
    __shared__ __align__(16) float As[8][128];
    __shared__ __align__(16) float Bs[8][128];
    const int tid  = threadIdx.x;
    const int row0 = blockIdx.y * 128;
    const int col0 = blockIdx.x * 128;

    const int ar = tid >> 1, ak = (tid & 1) * 4;    // A tile loader
    const int bk = tid >> 5, bn = (tid & 31) * 4;   // B tile loader
    const int tm8 = (tid >> 4) * 8, tn8 = (tid & 15) * 8;

    float acc[8][8];
#pragma unroll
    for (int i = 0; i < 8; i++)
#pragma unroll
        for (int j = 0; j < 8; j++) acc[i][j] = 0.0f;

    for (int k0 = 0; k0 < K; k0 += 8) {
        float4 av = make_float4(0.f, 0.f, 0.f, 0.f);
        int arow = row0 + ar;
        if (arow < M) av = *(const float4*)(A + (size_t)arow * K + k0 + ak);
        if (GELU) {
            av.x = gelu_f(av.x); av.y = gelu_f(av.y);
            av.z = gelu_f(av.z); av.w = gelu_f(av.w);
        }
        As[ak + 0][ar] = av.x; As[ak + 1][ar] = av.y;
        As[ak + 2][ar] = av.z; As[ak + 3][ar] = av.w;
        *(float4*)&Bs[bk][bn] =
            *(const float4*)(W + (size_t)(k0 + bk) * HD + col0 + bn);
        __syncthreads();
#pragma unroll
        for (int kk = 0; kk < 8; kk++) {
            float4 a0 = *(const float4*)&As[kk][tm8];
            float4 a1 = *(const float4*)&As[kk][tm8 + 4];
            float4 b0 = *(const float4*)&Bs[kk][tn8];
            float4 b1 = *(const float4*)&Bs[kk][tn8 + 4];
            float arr[8] = {a0.x, a0.y, a0.z, a0.w, a1.x, a1.y, a1.z, a1.w};
            float brr[8] = {b0.x, b0.y, b0.z, b0.w, b1.x, b1.y, b1.z, b1.w};
#pragma unroll
            for (int i = 0; i < 8; i++)
#pragma unroll
                for (int j = 0; j < 8; j++) acc[i][j] += arr[i] * brr[j];
        }
        __syncthreads();
    }
#pragma unroll
    for (int i = 0; i < 8; i++) {
        int r = row0 + tm8 + i;
        if (r < M) {
            float4 o0 = make_float4(acc[i][0], acc[i][1], acc[i][2], acc[i][3]);
            float4 o1 = make_float4(acc[i][4], acc[i][5], acc[i][6], acc[i][7]);
            float* cp = d_Hf + (size_t)r * HD + col0 + tn8;
            *(float4*)cp = o0;
            *(float4*)(cp + 4) = o1;
        }
    }
}

// ---------------- alpha dots: AS[n,h]=h[n,h,:]·a_src[h], AD likewise ----------------
__global__ void alpha_kernel(const float* __restrict__ a_src,
                             const float* __restrict__ a_dst) {
    int t = blockIdx.x * blockDim.x + threadIdx.x;
    int wid = t >> 5, lane = t & 31;
    if (wid >= Nn) return;
    const float4* hv = (const float4*)(d_Hf + (size_t)wid * HD);
    float4 v0 = hv[lane * 2], v1 = hv[lane * 2 + 1];
    const float4* s4 = (const float4*)a_src;
    const float4* d4 = (const float4*)a_dst;
    float4 w0 = s4[lane * 2], w1 = s4[lane * 2 + 1];
    float4 u0 = d4[lane * 2], u1 = d4[lane * 2 + 1];
    float ps = v0.x * w0.x + v0.y * w0.y + v0.z * w0.z + v0.w * w0.w +
               v1.x * w1.x + v1.y * w1.y + v1.z * w1.z + v1.w * w1.w;
    float pd = v0.x * u0.x + v0.y * u0.y + v0.z * u0.z + v0.w * u0.w +
               v1.x * u1.x + v1.y * u1.y + v1.z * u1.z + v1.w * u1.w;
#pragma unroll
    for (int off = 4; off; off >>= 1) {
        ps += __shfl_xor_sync(0xffffffffu, ps, off);
        pd += __shfl_xor_sync(0xffffffffu, pd, off);
    }
    if ((lane & 7) == 0) {
        d_ASf[wid * 4 + (lane >> 3)] = ps;
        d_ADf[wid * 4 + (lane >> 3)] = pd;
    }
}

// ---------------- per-edge weights: w = exp(leakyrelu(as[src]+ad[dst])) ----------------
__global__ void edgew_kernel() {
    int i = blockIdx.x * blockDim.x + threadIdx.x;
    if (i >= ET) return;
    int s = d_colsrc[i], d = d_colrow[i];
    float4 a = d_AS4[s], b = d_AD4[d];
    float e0 = a.x + b.x; e0 = e0 > 0.f ? e0 : 0.2f * e0;
    float e1 = a.y + b.y; e1 = e1 > 0.f ? e1 : 0.2f * e1;
    float e2 = a.z + b.z; e2 = e2 > 0.f ? e2 : 0.2f * e2;
    float e3 = a.w + b.w; e3 = e3 > 0.f ? e3 : 0.2f * e3;
    d_W44[i] = make_float4(expf(e0), expf(e1), expf(e2), expf(e3));
}

// ---------------- aggregation: OUT[d] = sum_e alpha_e * H[src_e] + bias ----------------
__global__ void agg_kernel(const float* __restrict__ bias) {
    int t = blockIdx.x * blockDim.x + threadIdx.x;
    int wid = t >> 5, lane = t & 31;
    if (wid >= Nn) return;
    int s0 = d_rowptr[wid], s1 = d_rowptr[wid + 1];
    int hh = lane >> 3;

    // deterministic serial z (per head, redundant across the 8 lanes of a head)
    float z = 0.f;
    for (int e = s0; e < s1; e++) z += d_W4f[e * 4 + hh];
    float invz = 1.f / (z + 1e-16f);

    float4 acc0 = make_float4(0.f, 0.f, 0.f, 0.f);
    float4 acc1 = make_float4(0.f, 0.f, 0.f, 0.f);
    for (int e = s0; e < s1; e++) {
        int s = d_colsrc[e];
        float w = d_W4f[e * 4 + hh] * invz;
        const float4* hp = (const float4*)(d_Hf + (size_t)s * HD + lane * 8);
        float4 v0 = hp[0], v1 = hp[1];
        acc0.x += w * v0.x; acc0.y += w * v0.y;
        acc0.z += w * v0.z; acc0.w += w * v0.w;
        acc1.x += w * v1.x; acc1.y += w * v1.y;
        acc1.z += w * v1.z; acc1.w += w * v1.w;
    }
    const float4* bp = (const float4*)(bias + lane * 8);
    float4 b0 = bp[0], b1 = bp[1];
    acc0.x += b0.x; acc0.y += b0.y; acc0.z += b0.z; acc0.w += b0.w;
    acc1.x += b1.x; acc1.y += b1.y; acc1.z += b1.z; acc1.w += b1.w;
    float* op = d_OUTf + (size_t)wid * HD + lane * 8;
    *(float4*)op = acc0;
    *(float4*)(op + 4) = acc1;
}

// ---------------- readout: per-graph [min|max|mean|sum] ----------------
__global__ void pool_kernel(const int* __restrict__ batch) {
    __shared__ int sb[2];
    int b = blockIdx.x, c = threadIdx.x;   // 256 threads = 256 cols
    if (c < 2) {
        int target = b + c;   // lower_bound(batch, target)
        int lo = 0, hi = Nn;
        while (lo < hi) {
            int mid = (lo + hi) >> 1;
            if (batch[mid] < target) lo = mid + 1; else hi = mid;
        }
        sb[c] = lo;
    }
    __syncthreads();
    int n0 = sb[0], n1 = sb[1];
    float mn = INFINITY, mx = -INFINITY, sm = 0.f;
    for (int n = n0; n < n1; n++) {
        float v = d_OUTf[(size_t)n * HD + c];
        mn = fminf(mn, v); mx = fmaxf(mx, v); sm += v;
    }
    int cnt = n1 - n0;
    if (cnt == 0) { mn = 0.f; mx = 0.f; }
    float mean = sm / fmaxf((float)cnt, 1.f);
    d_G[b * 1024 + c]       = mn;
    d_G[b * 1024 + 256 + c] = mx;
    d_G[b * 1024 + 512 + c] = mean;
    d_G[b * 1024 + 768 + c] = sm;
}

// ---------------- head: out = gelu(g) @ head_W + head_b ----------------
__global__ void head_kernel(const float* __restrict__ hW,
                            const float* __restrict__ hb,
                            float* __restrict__ out) {
    __shared__ float sg[1024];
    int b = blockIdx.x, j = threadIdx.x;   // 128 threads
    for (int k = j; k < 1024; k += 128) sg[k] = gelu_f(d_G[b * 1024 + k]);
    __syncthreads();
    float acc = hb[j];
    for (int k = 0; k < 1024; k++) acc += sg[k] * hW[k * NOUT + j];
    out[b * NOUT + j] = acc;
}

// ---------------- launch ----------------
extern "C" void kernel_launch(void* const* d_in, const int* in_sizes, int n_in,
                              void* d_out, int out_size) {
    const float* x      = (const float*)d_in[0];
    const int*   ei     = (const int*)  d_in[1];
    const int*   batch  = (const int*)  d_in[2];
    const float* W0     = (const float*)d_in[3];
    const float* a_src0 = (const float*)d_in[4];
    const float* a_dst0 = (const float*)d_in[5];
    const float* b0     = (const float*)d_in[6];
    const float* Ws     = (const float*)d_in[7];
    const float* a_srcs = (const float*)d_in[8];
    const float* a_dsts = (const float*)d_in[9];
    const float* bs     = (const float*)d_in[10];
    const float* hW     = (const float*)d_in[11];
    const float* hb     = (const float*)d_in[12];
    float* out = (float*)d_out;

    const int* srcp = ei;
    const int* dstp = ei + Ee;

    float* pOUT = nullptr;
    cudaGetSymbolAddress((void**)&pOUT, d_OUT4);

    deg_init_kernel<<<(Nn + 255) / 256, 256>>>();
    hist_kernel<<<(Ee + 255) / 256, 256>>>(dstp);
    scan_kernel<<<1, 1024>>>();
    scatter_kernel<<<(ET + 255) / 256, 256>>>(srcp, dstp);
    sort_rows_kernel<<<(Nn * 32 + 255) / 256, 256>>>();

    for (int l = 0; l < NL; l++) {
        const float* A  = l ? pOUT : x;
        const float* Wl = l ? Ws + (size_t)(l - 1) * HD * HD : W0;
        const float* as = l ? a_srcs + (size_t)(l - 1) * HD : a_src0;
        const float* ad = l ? a_dsts + (size_t)(l - 1) * HD : a_dst0;
        const float* bl = l ? bs + (size_t)(l - 1) * HD : b0;
        int K = l ? HD : NIN;
        dim3 grid(HD / 128, (Nn + 127) / 128);
        if (l) gemm_kernel<true ><<<grid, 256>>>(A, Wl, Nn, K);
        else   gemm_kernel<false><<<grid, 256>>>(A, Wl, Nn, K);
        alpha_kernel<<<(Nn * 32 + 255) / 256, 256>>>(as, ad);
        edgew_kernel<<<(ET + 255) / 256, 256>>>();
        agg_kernel<<<(Nn * 32 + 255) / 256, 256>>>(bl);
    }

    pool_kernel<<<Bb, 256>>>(batch);
    head_kernel<<<Bb, NOUT>>>(hW, hb, out);
}

// round 3
// speedup vs baseline: 1.6267x; 1.6267x over previous
#include <cuda_runtime.h>
#include <cuda_bf16.h>
#include <math.h>
#include <stdint.h>

#define Nn   30000
#define Ee   480000
#define ET   510000   // Ee + Nn self loops
#define Bb   48
#define HD   256      // H*D
#define NOUT 128
#define NL   10

// ---------------- device scratch (static, no allocs) ----------------
__device__ float4 d_H4[Nn * 64];     // H = X @ W        [N,256]
__device__ float4 d_OUT4[Nn * 64];   // layer output     [N,256]
__device__ float4 d_AS4[Nn];         // alpha_src        [N,4]
__device__ float4 d_AD4[Nn];         // alpha_dst        [N,4]
__device__ float4 d_W44[ET];         // per-edge exp weights [ET,4]
__device__ int    d_deg[Nn];
__device__ int    d_rowptr[Nn + 1];
__device__ int    d_cursor[Nn];
__device__ int    d_colsrc[ET];
__device__ int    d_colrow[ET];
__device__ float  d_G[Bb * 4 * HD];  // pooled [min|max|mean|sum]
// W split+transposed: [9 layers][hi|lo][n=256][k=256] bf16
__device__ __nv_bfloat16 d_Wsw[9 * 2 * 256 * 256];

#define d_Hf   ((float*)d_H4)
#define d_OUTf ((float*)d_OUT4)
#define d_ASf  ((float*)d_AS4)
#define d_ADf  ((float*)d_AD4)
#define d_W4f  ((float*)d_W44)

__device__ __forceinline__ float gelu_f(float x) {
    return 0.5f * x * (1.0f + erff(x * 0.70710678118654752f));
}

__device__ __forceinline__ uint32_t smem_u32(const void* p) {
    uint32_t a;
    asm("{ .reg .u64 t; cvta.to.shared.u64 t, %1; cvt.u32.u64 %0, t; }"
        : "=r"(a) : "l"(p));
    return a;
}
__device__ __forceinline__ void ldsm4(uint32_t* r, uint32_t addr) {
    asm volatile("ldmatrix.sync.aligned.m8n8.x4.shared.b16 {%0,%1,%2,%3}, [%4];"
                 : "=r"(r[0]), "=r"(r[1]), "=r"(r[2]), "=r"(r[3]) : "r"(addr));
}
__device__ __forceinline__ void mma16816(float* c, const uint32_t* a,
                                         const uint32_t* b) {
    asm volatile(
        "mma.sync.aligned.m16n8k16.row.col.f32.bf16.bf16.f32 "
        "{%0,%1,%2,%3}, {%4,%5,%6,%7}, {%8,%9}, {%0,%1,%2,%3};"
        : "+f"(c[0]), "+f"(c[1]), "+f"(c[2]), "+f"(c[3])
        : "r"(a[0]), "r"(a[1]), "r"(a[2]), "r"(a[3]), "r"(b[0]), "r"(b[1]));
}
__device__ __forceinline__ void cp16(uint32_t saddr, const void* gaddr) {
    asm volatile("cp.async.cg.shared.global [%0], [%1], 16;"
                 :: "r"(saddr), "l"(gaddr));
}
#define CP_COMMIT() asm volatile("cp.async.commit_group;" ::: "memory")
#define CP_WAIT1()  asm volatile("cp.async.wait_group 1;" ::: "memory")

// ---------------- CSR build ----------------
__global__ void deg_init_kernel() {
    int i = blockIdx.x * blockDim.x + threadIdx.x;
    if (i < Nn) d_deg[i] = 1;
}
__global__ void hist_kernel(const int* __restrict__ dst) {
    int i = blockIdx.x * blockDim.x + threadIdx.x;
    if (i < Ee) atomicAdd(&d_deg[dst[i]], 1);
}
__global__ void scan_kernel() {
    __shared__ int sh[1024];
    const int t = threadIdx.x;
    const int CH = (Nn + 1023) / 1024;
    int start = t * CH, end = min(start + CH, Nn);
    int s = 0;
    for (int i = start; i < end; i++) s += d_deg[i];
    sh[t] = s;
    __syncthreads();
    for (int off = 1; off < 1024; off <<= 1) {
        int v = (t >= off) ? sh[t - off] : 0;
        __syncthreads();
        sh[t] += v;
        __syncthreads();
    }
    int run = sh[t] - s;
    for (int i = start; i < end; i++) {
        d_rowptr[i] = run; d_cursor[i] = run; run += d_deg[i];
    }
    if (t == 1023) d_rowptr[Nn] = sh[1023];
}
__global__ void scatter_kernel(const int* __restrict__ src,
                               const int* __restrict__ dst) {
    int i = blockIdx.x * blockDim.x + threadIdx.x;
    if (i >= ET) return;
    int s, d;
    if (i < Ee) { s = src[i]; d = dst[i]; }
    else        { s = d = i - Ee; }
    int pos = atomicAdd(&d_cursor[d], 1);
    d_colsrc[pos] = s;
    d_colrow[pos] = d;
}
__global__ void sort_rows_kernel() {
    int t = blockIdx.x * blockDim.x + threadIdx.x;
    int wid = t >> 5, lane = t & 31;
    if (wid >= Nn) return;
    int s0 = d_rowptr[wid], s1 = d_rowptr[wid + 1];
    int n = s1 - s0;
    for (int p = 0; p < n; p++) {
        for (int i = (p & 1) + 2 * lane; i + 1 < n; i += 64) {
            int a = d_colsrc[s0 + i], b = d_colsrc[s0 + i + 1];
            if (a > b) { d_colsrc[s0 + i] = b; d_colsrc[s0 + i + 1] = a; }
        }
        __syncwarp();
    }
}

// ---------------- W split + transpose precompute: [l][hi|lo][n][k] ----------------
__global__ void wsplit_kernel(const float* __restrict__ Ws) {
    int idx = blockIdx.x * blockDim.x + threadIdx.x;   // 9*65536
    if (idx >= 9 * 65536) return;
    int l = idx >> 16;
    int rem = idx & 65535;
    int k = rem >> 8, n = rem & 255;
    float w = Ws[idx];
    __nv_bfloat16 hi = __float2bfloat16(w);
    __nv_bfloat16 lo = __float2bfloat16(w - __bfloat162float(hi));
    __nv_bfloat16* base = d_Wsw + (size_t)l * 131072;
    base[n * 256 + k] = hi;
    base[65536 + n * 256 + k] = lo;
}

// ---------------- layer 0 GEMM (K=8, fp32) ----------------
__global__ void layer0_kernel(const float* __restrict__ x,
                              const float* __restrict__ W0) {
    __shared__ float w[8 * 256];
    int t = threadIdx.x;
    for (int i = t; i < 2048; i += 256) w[i] = W0[i];
    __syncthreads();
    int g = blockIdx.x * 256 + t;
    if (g >= Nn * 64) return;
    int row = g >> 6, c4 = (g & 63) << 2;
    float xr[8];
#pragma unroll
    for (int k = 0; k < 8; k++) xr[k] = x[row * 8 + k];
    float4 acc = make_float4(0.f, 0.f, 0.f, 0.f);
#pragma unroll
    for (int k = 0; k < 8; k++) {
        float4 wv = *(const float4*)&w[k * 256 + c4];
        acc.x += xr[k] * wv.x; acc.y += xr[k] * wv.y;
        acc.z += xr[k] * wv.z; acc.w += xr[k] * wv.w;
    }
    *(float4*)(d_Hf + (size_t)row * HD + c4) = acc;
}

// ---------------- alpha dots (layer 0 only) ----------------
__global__ void alpha_kernel(const float* __restrict__ a_src,
                             const float* __restrict__ a_dst) {
    int t = blockIdx.x * blockDim.x + threadIdx.x;
    int wid = t >> 5, lane = t & 31;
    if (wid >= Nn) return;
    const float4* hv = (const float4*)(d_Hf + (size_t)wid * HD);
    float4 v0 = hv[lane * 2], v1 = hv[lane * 2 + 1];
    const float4* s4 = (const float4*)a_src;
    const float4* d4 = (const float4*)a_dst;
    float4 w0 = s4[lane * 2], w1 = s4[lane * 2 + 1];
    float4 u0 = d4[lane * 2], u1 = d4[lane * 2 + 1];
    float ps = v0.x * w0.x + v0.y * w0.y + v0.z * w0.z + v0.w * w0.w +
               v1.x * w1.x + v1.y * w1.y + v1.z * w1.z + v1.w * w1.w;
    float pd = v0.x * u0.x + v0.y * u0.y + v0.z * u0.z + v0.w * u0.w +
               v1.x * u1.x + v1.y * u1.y + v1.z * u1.z + v1.w * u1.w;
#pragma unroll
    for (int off = 4; off; off >>= 1) {
        ps += __shfl_xor_sync(0xffffffffu, ps, off);
        pd += __shfl_xor_sync(0xffffffffu, pd, off);
    }
    if ((lane & 7) == 0) {
        d_ASf[wid * 4 + (lane >> 3)] = ps;
        d_ADf[wid * 4 + (lane >> 3)] = pd;
    }
}

// ---------------- HMMA GEMM (layers 1..9): H = gelu(A) @ W, fused alpha ----------------
// SMEM map (bytes):
//   0      sa[256]                1024
//   1024   sd[256]                1024
//   2048   As_hi [128][pitch 80]  10240
//   12288  As_lo                  10240
//   22528  B buf0: hi 20480 | lo 20480   (pitch 80, 256 n-rows)
//   63488  B buf1: hi | lo
//   104448 Astage buf0 (fp32 128x32)     16384
//   120832 Astage buf1                   16384
#define SM_SA    0
#define SM_SD    1024
#define SM_AHI   2048
#define SM_ALO   12288
#define SM_B     22528
#define SM_BSTR  40960
#define SM_STAGE 104448
#define GEMM_SMEM 137216

__global__ void __launch_bounds__(256, 1)
gat_gemm_kernel(const float* __restrict__ A,
                const __nv_bfloat16* __restrict__ Wsw,
                const float* __restrict__ a_src,
                const float* __restrict__ a_dst) {
    extern __shared__ char smem[];
    const uint32_t sb = smem_u32(smem);
    const int tid = threadIdx.x;
    const int lane = tid & 31;
    const int wid = tid >> 5;
    const int WM = wid >> 2, WN = wid & 3;
    const int row0 = blockIdx.x * 128;

    float* sa = (float*)(smem + SM_SA);
    float* sd = (float*)(smem + SM_SD);
    sa[tid] = a_src[tid];
    sd[tid] = a_dst[tid];

    const char* Wbytes = (const char*)Wsw;

    // ---- prefetch chunk 0 ----
    {
        const int cc = 0;
#pragma unroll
        for (int j = 0; j < 8; j++) {
            int half = j >> 2;
            int idx = tid + (j & 3) * 256;
            int n = idx >> 2, sg = idx & 3;
            uint32_t dst = sb + SM_B + half * 20480 + n * 80 + sg * 16;
            cp16(dst, Wbytes + half * 131072 + n * 512 + cc * 64 + sg * 16);
        }
#pragma unroll
        for (int j = 0; j < 4; j++) {
            int idx = tid + j * 256;
            int row = idx >> 3, sg = idx & 7;
            int grow = row0 + row;
            uint32_t dst = sb + SM_STAGE + row * 128 + sg * 16;
            if (grow < Nn)
                cp16(dst, A + (size_t)grow * 256 + cc * 32 + sg * 4);
            else
                *(float4*)(smem + SM_STAGE + row * 128 + sg * 16) =
                    make_float4(0.f, 0.f, 0.f, 0.f);
        }
        CP_COMMIT();
    }

    float c[4][8][4];
#pragma unroll
    for (int mi = 0; mi < 4; mi++)
#pragma unroll
        for (int ni = 0; ni < 8; ni++)
#pragma unroll
            for (int q = 0; q < 4; q++) c[mi][ni][q] = 0.f;

    // per-thread ldmatrix base offsets
    const uint32_t aoff = (uint32_t)((WM * 64 + (lane & 15)) * 80 +
                                     (lane >> 4) * 16);
    const uint32_t boff = (uint32_t)((WN * 64 + ((lane >> 4) & 1) * 8 +
                                      (lane & 7)) * 80 +
                                     ((lane >> 3) & 1) * 16);

    for (int cchunk = 0; cchunk < 8; cchunk++) {
        const int buf = cchunk & 1;
        __syncthreads();   // mma(c-1) everywhere done: buf^1 + As free

        if (cchunk < 7) {
            const int cc = cchunk + 1;
            const int pb = cc & 1;
#pragma unroll
            for (int j = 0; j < 8; j++) {
                int half = j >> 2;
                int idx = tid + (j & 3) * 256;
                int n = idx >> 2, sg = idx & 3;
                uint32_t dst = sb + SM_B + pb * SM_BSTR + half * 20480 +
                               n * 80 + sg * 16;
                cp16(dst, Wbytes + half * 131072 + n * 512 + cc * 64 + sg * 16);
            }
#pragma unroll
            for (int j = 0; j < 4; j++) {
                int idx = tid + j * 256;
                int row = idx >> 3, sg = idx & 7;
                int grow = row0 + row;
                uint32_t dst = sb + SM_STAGE + pb * 16384 + row * 128 + sg * 16;
                if (grow < Nn)
                    cp16(dst, A + (size_t)grow * 256 + cc * 32 + sg * 4);
                else
                    *(float4*)(smem + SM_STAGE + pb * 16384 + row * 128 +
                               sg * 16) = make_float4(0.f, 0.f, 0.f, 0.f);
            }
        }
        CP_COMMIT();
        CP_WAIT1();
        __syncthreads();   // chunk data visible to all

        // ---- convert Astage[buf] -> As_hi/As_lo (gelu + bf16 split) ----
        {
            const char* stg = smem + SM_STAGE + buf * 16384;
#pragma unroll
            for (int j = 0; j < 4; j++) {
                int idx = tid + j * 256;
                int row = idx >> 3, kv = (idx & 7) * 4;
                float4 v = *(const float4*)(stg + row * 128 + kv * 4);
                v.x = gelu_f(v.x); v.y = gelu_f(v.y);
                v.z = gelu_f(v.z); v.w = gelu_f(v.w);
                __nv_bfloat16 h0 = __float2bfloat16(v.x);
                __nv_bfloat16 h1 = __float2bfloat16(v.y);
                __nv_bfloat16 h2 = __float2bfloat16(v.z);
                __nv_bfloat16 h3 = __float2bfloat16(v.w);
                __nv_bfloat16 l0 = __float2bfloat16(v.x - __bfloat162float(h0));
                __nv_bfloat16 l1 = __float2bfloat16(v.y - __bfloat162float(h1));
                __nv_bfloat16 l2 = __float2bfloat16(v.z - __bfloat162float(h2));
                __nv_bfloat16 l3 = __float2bfloat16(v.w - __bfloat162float(h3));
                uint64_t hp = (uint64_t)__bfloat16_as_ushort(h0) |
                              ((uint64_t)__bfloat16_as_ushort(h1) << 16) |
                              ((uint64_t)__bfloat16_as_ushort(h2) << 32) |
                              ((uint64_t)__bfloat16_as_ushort(h3) << 48);
                uint64_t lp = (uint64_t)__bfloat16_as_ushort(l0) |
                              ((uint64_t)__bfloat16_as_ushort(l1) << 16) |
                              ((uint64_t)__bfloat16_as_ushort(l2) << 32) |
                              ((uint64_t)__bfloat16_as_ushort(l3) << 48);
                *(uint64_t*)(smem + SM_AHI + row * 80 + kv * 2) = hp;
                *(uint64_t*)(smem + SM_ALO + row * 80 + kv * 2) = lp;
            }
        }
        __syncthreads();

        // ---- MMA: 2 k16-steps, 3 products ----
        const uint32_t aH = sb + SM_AHI, aL = sb + SM_ALO;
        const uint32_t bH = sb + SM_B + buf * SM_BSTR;
        const uint32_t bL = bH + 20480;
#pragma unroll
        for (int s = 0; s < 2; s++) {
            const uint32_t so = (uint32_t)(s * 32);
            uint32_t ah[4][4], bh[4][4];
#pragma unroll
            for (int mi = 0; mi < 4; mi++)
                ldsm4(ah[mi], aH + aoff + mi * 1280 + so);
#pragma unroll
            for (int p = 0; p < 4; p++)
                ldsm4(bh[p], bH + boff + p * 1280 + so);
#pragma unroll
            for (int mi = 0; mi < 4; mi++)
#pragma unroll
                for (int ni = 0; ni < 8; ni++)
                    mma16816(c[mi][ni], ah[mi], &bh[ni >> 1][(ni & 1) * 2]);
            uint32_t bl[4][4];
#pragma unroll
            for (int p = 0; p < 4; p++)
                ldsm4(bl[p], bL + boff + p * 1280 + so);
#pragma unroll
            for (int mi = 0; mi < 4; mi++)
#pragma unroll
                for (int ni = 0; ni < 8; ni++)
                    mma16816(c[mi][ni], ah[mi], &bl[ni >> 1][(ni & 1) * 2]);
            uint32_t al[4][4];
#pragma unroll
            for (int mi = 0; mi < 4; mi++)
                ldsm4(al[mi], aL + aoff + mi * 1280 + so);
#pragma unroll
            for (int mi = 0; mi < 4; mi++)
#pragma unroll
                for (int ni = 0; ni < 8; ni++)
                    mma16816(c[mi][ni], al[mi], &bh[ni >> 1][(ni & 1) * 2]);
        }
    }

    // ---- epilogue: fused alpha dots + H writeback ----
    const int colq = WN * 64 + (lane & 3) * 2;
#pragma unroll
    for (int mi = 0; mi < 4; mi++) {
#pragma unroll
        for (int h = 0; h < 2; h++) {
            float ps = 0.f, pd = 0.f;
#pragma unroll
            for (int ni = 0; ni < 8; ni++) {
                float v0 = c[mi][ni][h * 2], v1 = c[mi][ni][h * 2 + 1];
                int col = colq + ni * 8;
                ps += v0 * sa[col] + v1 * sa[col + 1];
                pd += v0 * sd[col] + v1 * sd[col + 1];
            }
            ps += __shfl_xor_sync(0xffffffffu, ps, 1);
            ps += __shfl_xor_sync(0xffffffffu, ps, 2);
            pd += __shfl_xor_sync(0xffffffffu, pd, 1);
            pd += __shfl_xor_sync(0xffffffffu, pd, 2);
            int row = row0 + WM * 64 + mi * 16 + h * 8 + (lane >> 2);
            if ((lane & 3) == 0 && row < Nn) {
                d_ASf[row * 4 + WN] = ps;
                d_ADf[row * 4 + WN] = pd;
            }
        }
    }
#pragma unroll
    for (int mi = 0; mi < 4; mi++) {
#pragma unroll
        for (int h = 0; h < 2; h++) {
            int row = row0 + WM * 64 + mi * 16 + h * 8 + (lane >> 2);
            if (row >= Nn) continue;
            float* op = d_Hf + (size_t)row * HD;
#pragma unroll
            for (int ni = 0; ni < 8; ni++) {
                float2 v = make_float2(c[mi][ni][h * 2], c[mi][ni][h * 2 + 1]);
                *(float2*)(op + colq + ni * 8) = v;
            }
        }
    }
}

// ---------------- per-edge weights ----------------
__global__ void edgew_kernel() {
    int i = blockIdx.x * blockDim.x + threadIdx.x;
    if (i >= ET) return;
    int s = d_colsrc[i], d = d_colrow[i];
    float4 a = d_AS4[s], b = d_AD4[d];
    float e0 = a.x + b.x; e0 = e0 > 0.f ? e0 : 0.2f * e0;
    float e1 = a.y + b.y; e1 = e1 > 0.f ? e1 : 0.2f * e1;
    float e2 = a.z + b.z; e2 = e2 > 0.f ? e2 : 0.2f * e2;
    float e3 = a.w + b.w; e3 = e3 > 0.f ? e3 : 0.2f * e3;
    d_W44[i] = make_float4(expf(e0), expf(e1), expf(e2), expf(e3));
}

// ---------------- aggregation ----------------
__global__ void agg_kernel(const float* __restrict__ bias) {
    int t = blockIdx.x * blockDim.x + threadIdx.x;
    int wid = t >> 5, lane = t & 31;
    if (wid >= Nn) return;
    int s0 = d_rowptr[wid], s1 = d_rowptr[wid + 1];
    int hh = lane >> 3;

    float z = 0.f;
    for (int e = s0; e < s1; e++) z += d_W4f[e * 4 + hh];
    float invz = 1.f / (z + 1e-16f);

    float4 acc0 = make_float4(0.f, 0.f, 0.f, 0.f);
    float4 acc1 = make_float4(0.f, 0.f, 0.f, 0.f);
    for (int e = s0; e < s1; e++) {
        int s = d_colsrc[e];
        float w = d_W4f[e * 4 + hh] * invz;
        const float4* hp = (const float4*)(d_Hf + (size_t)s * HD + lane * 8);
        float4 v0 = hp[0], v1 = hp[1];
        acc0.x += w * v0.x; acc0.y += w * v0.y;
        acc0.z += w * v0.z; acc0.w += w * v0.w;
        acc1.x += w * v1.x; acc1.y += w * v1.y;
        acc1.z += w * v1.z; acc1.w += w * v1.w;
    }
    const float4* bp = (const float4*)(bias + lane * 8);
    float4 b0 = bp[0], b1 = bp[1];
    acc0.x += b0.x; acc0.y += b0.y; acc0.z += b0.z; acc0.w += b0.w;
    acc1.x += b1.x; acc1.y += b1.y; acc1.z += b1.z; acc1.w += b1.w;
    float* op = d_OUTf + (size_t)wid * HD + lane * 8;
    *(float4*)op = acc0;
    *(float4*)(op + 4) = acc1;
}

// ---------------- readout ----------------
__global__ void pool_kernel(const int* __restrict__ batch) {
    __shared__ int sbm[2];
    int b = blockIdx.x, c = threadIdx.x;
    if (c < 2) {
        int target = b + c;
        int lo = 0, hi = Nn;
        while (lo < hi) {
            int mid = (lo + hi) >> 1;
            if (batch[mid] < target) lo = mid + 1; else hi = mid;
        }
        sbm[c] = lo;
    }
    __syncthreads();
    int n0 = sbm[0], n1 = sbm[1];
    float mn = INFINITY, mx = -INFINITY, sm = 0.f;
    for (int n = n0; n < n1; n++) {
        float v = d_OUTf[(size_t)n * HD + c];
        mn = fminf(mn, v); mx = fmaxf(mx, v); sm += v;
    }
    int cnt = n1 - n0;
    if (cnt == 0) { mn = 0.f; mx = 0.f; }
    float mean = sm / fmaxf((float)cnt, 1.f);
    d_G[b * 1024 + c]       = mn;
    d_G[b * 1024 + 256 + c] = mx;
    d_G[b * 1024 + 512 + c] = mean;
    d_G[b * 1024 + 768 + c] = sm;
}

__global__ void head_kernel(const float* __restrict__ hW,
                            const float* __restrict__ hb,
                            float* __restrict__ out) {
    __shared__ float sg[1024];
    int b = blockIdx.x, j = threadIdx.x;
    for (int k = j; k < 1024; k += 128) sg[k] = gelu_f(d_G[b * 1024 + k]);
    __syncthreads();
    float acc = hb[j];
    for (int k = 0; k < 1024; k++) acc += sg[k] * hW[k * NOUT + j];
    out[b * NOUT + j] = acc;
}

// ---------------- launch ----------------
extern "C" void kernel_launch(void* const* d_in, const int* in_sizes, int n_in,
                              void* d_out, int out_size) {
    const float* x      = (const float*)d_in[0];
    const int*   ei     = (const int*)  d_in[1];
    const int*   batch  = (const int*)  d_in[2];
    const float* W0     = (const float*)d_in[3];
    const float* a_src0 = (const float*)d_in[4];
    const float* a_dst0 = (const float*)d_in[5];
    const float* b0     = (const float*)d_in[6];
    const float* Ws     = (const float*)d_in[7];
    const float* a_srcs = (const float*)d_in[8];
    const float* a_dsts = (const float*)d_in[9];
    const float* bs     = (const float*)d_in[10];
    const float* hW     = (const float*)d_in[11];
    const float* hb     = (const float*)d_in[12];
    float* out = (float*)d_out;

    const int* srcp = ei;
    const int* dstp = ei + Ee;

    float* pOUT = nullptr;
    cudaGetSymbolAddress((void**)&pOUT, d_OUT4);
    __nv_bfloat16* pWsw = nullptr;
    cudaGetSymbolAddress((void**)&pWsw, d_Wsw);

    cudaFuncSetAttribute(gat_gemm_kernel,
                         cudaFuncAttributeMaxDynamicSharedMemorySize, GEMM_SMEM);

    deg_init_kernel<<<(Nn + 255) / 256, 256>>>();
    hist_kernel<<<(Ee + 255) / 256, 256>>>(dstp);
    scan_kernel<<<1, 1024>>>();
    scatter_kernel<<<(ET + 255) / 256, 256>>>(srcp, dstp);
    sort_rows_kernel<<<(Nn * 32 + 255) / 256, 256>>>();
    wsplit_kernel<<<(9 * 65536 + 255) / 256, 256>>>(Ws);

    // layer 0
    layer0_kernel<<<(Nn * 64 + 255) / 256, 256>>>(x, W0);
    alpha_kernel<<<(Nn * 32 + 255) / 256, 256>>>(a_src0, a_dst0);
    edgew_kernel<<<(ET + 255) / 256, 256>>>();
    agg_kernel<<<(Nn * 32 + 255) / 256, 256>>>(b0);

    // layers 1..9
    for (int l = 1; l < NL; l++) {
        gat_gemm_kernel<<<(Nn + 127) / 128, 256, GEMM_SMEM>>>(
            pOUT, pWsw + (size_t)(l - 1) * 131072,
            a_srcs + (size_t)(l - 1) * HD, a_dsts + (size_t)(l - 1) * HD);
        edgew_kernel<<<(ET + 255) / 256, 256>>>();
        agg_kernel<<<(Nn * 32 + 255) / 256, 256>>>(bs + (size_t)(l - 1) * HD);
    }

    pool_kernel<<<Bb, 256>>>(batch);
    head_kernel<<<Bb, NOUT>>>(hW, hb, out);
}

// round 4
// speedup vs baseline: 1.6479x; 1.0130x over previous
#include <cuda_runtime.h>
#include <cuda_bf16.h>
#include <math.h>
#include <stdint.h>

#define Nn   30000
#define NnP  30080     // padded to 235*128 for GEMM tiles
#define Ee   480000
#define ET   510000    // Ee + Nn self loops
#define Bb   48
#define HD   256       // H*D
#define NOUT 128
#define NL   10

// ---------------- device scratch (static, no allocs) ----------------
__device__ float4 d_H4[Nn * 64];       // H = gelu(prev) @ W   [N,256] fp32
__device__ float4 d_OUT4[Nn * 64];     // final layer output (pool input)
__device__ float4 d_AS4[Nn];           // alpha_src [N,4]
__device__ float4 d_AD4[Nn];           // alpha_dst [N,4]
__device__ int    d_deg[Nn];
__device__ int    d_rowptr[Nn + 1];
__device__ int    d_cursor[Nn];
__device__ int    d_colsrc[ET];
__device__ float  d_G[Bb * 4 * HD];    // pooled [min|max|mean|sum]
// gelu(agg out) bf16 split, GEMM A input: [NnP][256]
__device__ __nv_bfloat16 d_Gh[NnP * 256];
__device__ __nv_bfloat16 d_Gl[NnP * 256];
// W split+transposed: [9 layers][hi|lo][n=256][k=256] bf16
__device__ __nv_bfloat16 d_Wsw[9 * 2 * 256 * 256];

#define d_Hf   ((float*)d_H4)
#define d_OUTf ((float*)d_OUT4)
#define d_ASf  ((float*)d_AS4)
#define d_ADf  ((float*)d_AD4)

__device__ __forceinline__ float gelu_f(float x) {
    return 0.5f * x * (1.0f + erff(x * 0.70710678118654752f));
}
__device__ __forceinline__ uint32_t smem_u32(const void* p) {
    uint32_t a;
    asm("{ .reg .u64 t; cvta.to.shared.u64 t, %1; cvt.u32.u64 %0, t; }"
        : "=r"(a) : "l"(p));
    return a;
}
__device__ __forceinline__ void ldsm4(uint32_t* r, uint32_t addr) {
    asm volatile("ldmatrix.sync.aligned.m8n8.x4.shared.b16 {%0,%1,%2,%3}, [%4];"
                 : "=r"(r[0]), "=r"(r[1]), "=r"(r[2]), "=r"(r[3]) : "r"(addr));
}
__device__ __forceinline__ void mma16816(float* c, const uint32_t* a,
                                         const uint32_t* b) {
    asm volatile(
        "mma.sync.aligned.m16n8k16.row.col.f32.bf16.bf16.f32 "
        "{%0,%1,%2,%3}, {%4,%5,%6,%7}, {%8,%9}, {%0,%1,%2,%3};"
        : "+f"(c[0]), "+f"(c[1]), "+f"(c[2]), "+f"(c[3])
        : "r"(a[0]), "r"(a[1]), "r"(a[2]), "r"(a[3]), "r"(b[0]), "r"(b[1]));
}
__device__ __forceinline__ void cp16(uint32_t saddr, const void* gaddr) {
    asm volatile("cp.async.cg.shared.global [%0], [%1], 16;"
                 :: "r"(saddr), "l"(gaddr));
}
#define CP_COMMIT() asm volatile("cp.async.commit_group;" ::: "memory")
#define CP_WAIT1()  asm volatile("cp.async.wait_group 1;" ::: "memory")
#define CP_WAIT0()  asm volatile("cp.async.wait_group 0;" ::: "memory")

// ---------------- CSR build ----------------
__global__ void deg_init_kernel() {
    int i = blockIdx.x * blockDim.x + threadIdx.x;
    if (i < Nn) d_deg[i] = 1;
}
__global__ void hist_kernel(const int* __restrict__ dst) {
    int i = blockIdx.x * blockDim.x + threadIdx.x;
    if (i < Ee) atomicAdd(&d_deg[dst[i]], 1);
}
__global__ void scan_kernel() {
    __shared__ int sh[1024];
    const int t = threadIdx.x;
    const int CH = (Nn + 1023) / 1024;
    int start = t * CH, end = min(start + CH, Nn);
    int s = 0;
    for (int i = start; i < end; i++) s += d_deg[i];
    sh[t] = s;
    __syncthreads();
    for (int off = 1; off < 1024; off <<= 1) {
        int v = (t >= off) ? sh[t - off] : 0;
        __syncthreads();
        sh[t] += v;
        __syncthreads();
    }
    int run = sh[t] - s;
    for (int i = start; i < end; i++) {
        d_rowptr[i] = run; d_cursor[i] = run; run += d_deg[i];
    }
    if (t == 1023) d_rowptr[Nn] = sh[1023];
}
__global__ void scatter_kernel(const int* __restrict__ src,
                               const int* __restrict__ dst) {
    int i = blockIdx.x * blockDim.x + threadIdx.x;
    if (i >= ET) return;
    int s, d;
    if (i < Ee) { s = src[i]; d = dst[i]; }
    else        { s = d = i - Ee; }
    int pos = atomicAdd(&d_cursor[d], 1);
    d_colsrc[pos] = s;
}
__global__ void sort_rows_kernel() {
    int t = blockIdx.x * blockDim.x + threadIdx.x;
    int wid = t >> 5, lane = t & 31;
    if (wid >= Nn) return;
    int s0 = d_rowptr[wid], s1 = d_rowptr[wid + 1];
    int n = s1 - s0;
    for (int p = 0; p < n; p++) {
        for (int i = (p & 1) + 2 * lane; i + 1 < n; i += 64) {
            int a = d_colsrc[s0 + i], b = d_colsrc[s0 + i + 1];
            if (a > b) { d_colsrc[s0 + i] = b; d_colsrc[s0 + i + 1] = a; }
        }
        __syncwarp();
    }
}

// ---------------- W split + transpose precompute: [l][hi|lo][n][k] ----------------
__global__ void wsplit_kernel(const float* __restrict__ Ws) {
    int idx = blockIdx.x * blockDim.x + threadIdx.x;   // 9*65536
    if (idx >= 9 * 65536) return;
    int l = idx >> 16;
    int rem = idx & 65535;
    int k = rem >> 8, n = rem & 255;
    float w = Ws[idx];
    __nv_bfloat16 hi = __float2bfloat16(w);
    __nv_bfloat16 lo = __float2bfloat16(w - __bfloat162float(hi));
    __nv_bfloat16* base = d_Wsw + (size_t)l * 131072;
    base[n * 256 + k] = hi;
    base[65536 + n * 256 + k] = lo;
}

// ---------------- layer 0: H0 = x @ W0, fused alpha dots (warp/row) ----------------
__global__ void layer0_kernel(const float* __restrict__ x,
                              const float* __restrict__ W0,
                              const float* __restrict__ a_src,
                              const float* __restrict__ a_dst) {
    __shared__ float w[8 * 256];
    __shared__ float sa[256], sd[256];
    int t = threadIdx.x;
    for (int i = t; i < 2048; i += 256) w[i] = W0[i];
    sa[t] = a_src[t];
    sd[t] = a_dst[t];
    __syncthreads();
    int lane = t & 31;
    int row = blockIdx.x * 8 + (t >> 5);
    float xr[8];
#pragma unroll
    for (int k = 0; k < 8; k++) xr[k] = __ldg(x + row * 8 + k);
    float ps[4] = {0.f, 0.f, 0.f, 0.f}, pd[4] = {0.f, 0.f, 0.f, 0.f};
    float* op = d_Hf + (size_t)row * HD;
#pragma unroll
    for (int j = 0; j < 8; j++) {
        int col = lane + 32 * j;
        float acc = 0.f;
#pragma unroll
        for (int k = 0; k < 8; k++) acc += xr[k] * w[k * 256 + col];
        op[col] = acc;
        ps[j >> 1] += acc * sa[col];
        pd[j >> 1] += acc * sd[col];
    }
#pragma unroll
    for (int h = 0; h < 4; h++) {
#pragma unroll
        for (int off = 16; off; off >>= 1) {
            ps[h] += __shfl_xor_sync(0xffffffffu, ps[h], off);
            pd[h] += __shfl_xor_sync(0xffffffffu, pd[h], off);
        }
    }
    if (lane < 4) {
        d_ASf[row * 4 + lane] = ps[lane];
        d_ADf[row * 4 + lane] = pd[lane];
    }
}

// ---------------- HMMA GEMM (layers 1..9): H = (Gh+Gl) @ (Wh+Wl), fused alpha ----------
// SMEM: sa 1024 | sd 1024 | 2 buffers x 61440:
//   buf: Ahi 10240 | Alo 10240 | Bhi 20480 | Blo 20480   (pitch-80 rows)
#define SM_SA    0
#define SM_SD    1024
#define SM_BUF   2048
#define SM_BSTR  61440
#define GEMM_SMEM (2048 + 2 * 61440)

__global__ void __launch_bounds__(256, 1)
gat_gemm_kernel(const __nv_bfloat16* __restrict__ Wsw,
                const float* __restrict__ a_src,
                const float* __restrict__ a_dst) {
    extern __shared__ char smem[];
    const uint32_t sb = smem_u32(smem);
    const int tid = threadIdx.x;
    const int lane = tid & 31;
    const int wid = tid >> 5;
    const int WM = wid >> 2, WN = wid & 3;
    const int row0 = blockIdx.x * 128;

    float* sa = (float*)(smem + SM_SA);
    float* sd = (float*)(smem + SM_SD);
    sa[tid] = a_src[tid];
    sd[tid] = a_dst[tid];

    const char* Wb = (const char*)Wsw;
    const char* Ah = (const char*)d_Gh;
    const char* Al = (const char*)d_Gl;

    // prefetch helper as lambda-style macro
#define PREFETCH(cc) do {                                                     \
    const int _pb = (cc) & 1;                                                 \
    const uint32_t _bs = sb + SM_BUF + _pb * SM_BSTR;                         \
    _Pragma("unroll")                                                         \
    for (int j = 0; j < 4; j++) {        /* A: 2 arrays x 512 cp16 */        \
        int half = j >> 1;                                                    \
        int idx = tid + (j & 1) * 256;   /* 0..511 */                        \
        int row = idx >> 2, sg = idx & 3;                                     \
        uint32_t dst = _bs + half * 10240 + row * 80 + sg * 16;               \
        const char* srcb = half ? Al : Ah;                                    \
        cp16(dst, srcb + (size_t)(row0 + row) * 512 + (cc) * 64 + sg * 16);   \
    }                                                                         \
    _Pragma("unroll")                                                         \
    for (int j = 0; j < 8; j++) {        /* B: 2 arrays x 1024 cp16 */       \
        int half = j >> 2;                                                    \
        int idx = tid + (j & 3) * 256;   /* 0..1023 */                       \
        int n = idx >> 2, sg = idx & 3;                                       \
        uint32_t dst = _bs + 20480 + half * 20480 + n * 80 + sg * 16;         \
        cp16(dst, Wb + half * 131072 + n * 512 + (cc) * 64 + sg * 16);        \
    }                                                                         \
    CP_COMMIT();                                                              \
} while (0)

    PREFETCH(0);

    float c[4][8][4];
#pragma unroll
    for (int mi = 0; mi < 4; mi++)
#pragma unroll
        for (int ni = 0; ni < 8; ni++)
#pragma unroll
            for (int q = 0; q < 4; q++) c[mi][ni][q] = 0.f;

    const uint32_t aoff = (uint32_t)((WM * 64 + (lane & 15)) * 80 +
                                     (lane >> 4) * 16);
    const uint32_t boff = (uint32_t)((WN * 64 + ((lane >> 4) & 1) * 8 +
                                      (lane & 7)) * 80 +
                                     ((lane >> 3) & 1) * 16);

    for (int cc = 0; cc < 8; cc++) {
        const int buf = cc & 1;
        __syncthreads();            // all warps done with mma(cc-1)
        if (cc < 7) { PREFETCH(cc + 1); CP_WAIT1(); }
        else        { CP_WAIT0(); }
        __syncthreads();            // chunk cc visible to all threads

        const uint32_t bs = sb + SM_BUF + buf * SM_BSTR;
        const uint32_t aH = bs, aL = bs + 10240;
        const uint32_t bH = bs + 20480, bL = bs + 40960;
#pragma unroll
        for (int s = 0; s < 2; s++) {
            const uint32_t so = (uint32_t)(s * 32);
            uint32_t ah[4][4], bh[4][4];
#pragma unroll
            for (int mi = 0; mi < 4; mi++)
                ldsm4(ah[mi], aH + aoff + mi * 1280 + so);
#pragma unroll
            for (int p = 0; p < 4; p++)
                ldsm4(bh[p], bH + boff + p * 1280 + so);
#pragma unroll
            for (int mi = 0; mi < 4; mi++)
#pragma unroll
                for (int ni = 0; ni < 8; ni++)
                    mma16816(c[mi][ni], ah[mi], &bh[ni >> 1][(ni & 1) * 2]);
            uint32_t bl[4][4];
#pragma unroll
            for (int p = 0; p < 4; p++)
                ldsm4(bl[p], bL + boff + p * 1280 + so);
#pragma unroll
            for (int mi = 0; mi < 4; mi++)
#pragma unroll
                for (int ni = 0; ni < 8; ni++)
                    mma16816(c[mi][ni], ah[mi], &bl[ni >> 1][(ni & 1) * 2]);
            uint32_t al[4][4];
#pragma unroll
            for (int mi = 0; mi < 4; mi++)
                ldsm4(al[mi], aL + aoff + mi * 1280 + so);
#pragma unroll
            for (int mi = 0; mi < 4; mi++)
#pragma unroll
                for (int ni = 0; ni < 8; ni++)
                    mma16816(c[mi][ni], al[mi], &bh[ni >> 1][(ni & 1) * 2]);
        }
    }
#undef PREFETCH

    // ---- epilogue: fused alpha dots + H writeback ----
    const int colq = WN * 64 + (lane & 3) * 2;
#pragma unroll
    for (int mi = 0; mi < 4; mi++) {
#pragma unroll
        for (int h = 0; h < 2; h++) {
            float ps = 0.f, pd = 0.f;
#pragma unroll
            for (int ni = 0; ni < 8; ni++) {
                float v0 = c[mi][ni][h * 2], v1 = c[mi][ni][h * 2 + 1];
                int col = colq + ni * 8;
                ps += v0 * sa[col] + v1 * sa[col + 1];
                pd += v0 * sd[col] + v1 * sd[col + 1];
            }
            ps += __shfl_xor_sync(0xffffffffu, ps, 1);
            ps += __shfl_xor_sync(0xffffffffu, ps, 2);
            pd += __shfl_xor_sync(0xffffffffu, pd, 1);
            pd += __shfl_xor_sync(0xffffffffu, pd, 2);
            int row = row0 + WM * 64 + mi * 16 + h * 8 + (lane >> 2);
            if ((lane & 3) == 0 && row < Nn) {
                d_ASf[row * 4 + WN] = ps;
                d_ADf[row * 4 + WN] = pd;
            }
        }
    }
#pragma unroll
    for (int mi = 0; mi < 4; mi++) {
#pragma unroll
        for (int h = 0; h < 2; h++) {
            int row = row0 + WM * 64 + mi * 16 + h * 8 + (lane >> 2);
            if (row >= Nn) continue;
            float* op = d_Hf + (size_t)row * HD;
#pragma unroll
            for (int ni = 0; ni < 8; ni++) {
                float2 v = make_float2(c[mi][ni][h * 2], c[mi][ni][h * 2 + 1]);
                *(float2*)(op + colq + ni * 8) = v;
            }
        }
    }
}

// ---------------- aggregation (fused softmax weights + gelu-split epilogue) -------
template <bool LAST>
__global__ void agg_kernel(const float* __restrict__ bias) {
    int t = blockIdx.x * blockDim.x + threadIdx.x;
    int row = t >> 5, lane = t & 31;
    if (row >= Nn) return;
    const int hh = lane >> 3, sub = lane & 7;
    const int s0 = d_rowptr[row], s1 = d_rowptr[row + 1];

    float4 adv = d_AD4[row];
    const float ad = (hh == 0) ? adv.x : (hh == 1) ? adv.y
                   : (hh == 2) ? adv.z : adv.w;

    // pass 1: z per head (8 lanes per head stride the edges; fixed shfl tree)
    float z = 0.f;
    for (int e = s0 + sub; e < s1; e += 8) {
        int sidx = d_colsrc[e];
        float as = d_ASf[sidx * 4 + hh];
        float tt = as + ad;
        tt = tt > 0.f ? tt : 0.2f * tt;
        z += expf(tt);
    }
    z += __shfl_xor_sync(0xffffffffu, z, 1);
    z += __shfl_xor_sync(0xffffffffu, z, 2);
    z += __shfl_xor_sync(0xffffffffu, z, 4);
    const float invz = 1.f / (z + 1e-16f);

    // pass 2: weighted gather (serial edge order, lane-owned columns)
    float4 acc0 = make_float4(0.f, 0.f, 0.f, 0.f);
    float4 acc1 = make_float4(0.f, 0.f, 0.f, 0.f);
    for (int e = s0; e < s1; e++) {
        int sidx = d_colsrc[e];
        float4 asv = d_AS4[sidx];
        float a = (hh == 0) ? asv.x : (hh == 1) ? asv.y
                : (hh == 2) ? asv.z : asv.w;
        float tt = a + ad;
        tt = tt > 0.f ? tt : 0.2f * tt;
        float wgt = expf(tt) * invz;
        const float4* hp = d_H4 + (size_t)sidx * 64 + lane * 2;
        float4 v0 = hp[0], v1 = hp[1];
        acc0.x += wgt * v0.x; acc0.y += wgt * v0.y;
        acc0.z += wgt * v0.z; acc0.w += wgt * v0.w;
        acc1.x += wgt * v1.x; acc1.y += wgt * v1.y;
        acc1.z += wgt * v1.z; acc1.w += wgt * v1.w;
    }
    const float4* bp = (const float4*)(bias + lane * 8);
    float4 b0 = bp[0], b1 = bp[1];
    acc0.x += b0.x; acc0.y += b0.y; acc0.z += b0.z; acc0.w += b0.w;
    acc1.x += b1.x; acc1.y += b1.y; acc1.z += b1.z; acc1.w += b1.w;

    if (LAST) {
        float* op = d_OUTf + (size_t)row * HD + lane * 8;
        *(float4*)op = acc0;
        *(float4*)(op + 4) = acc1;
    } else {
        float g[8] = {acc0.x, acc0.y, acc0.z, acc0.w,
                      acc1.x, acc1.y, acc1.z, acc1.w};
        uint16_t hi[8], lo[8];
#pragma unroll
        for (int q = 0; q < 8; q++) {
            float gv = gelu_f(g[q]);
            __nv_bfloat16 h = __float2bfloat16(gv);
            hi[q] = __bfloat16_as_ushort(h);
            lo[q] = __bfloat16_as_ushort(
                __float2bfloat16(gv - __bfloat162float(h)));
        }
        uint4 hp, lp;
        hp.x = (uint32_t)hi[0] | ((uint32_t)hi[1] << 16);
        hp.y = (uint32_t)hi[2] | ((uint32_t)hi[3] << 16);
        hp.z = (uint32_t)hi[4] | ((uint32_t)hi[5] << 16);
        hp.w = (uint32_t)hi[6] | ((uint32_t)hi[7] << 16);
        lp.x = (uint32_t)lo[0] | ((uint32_t)lo[1] << 16);
        lp.y = (uint32_t)lo[2] | ((uint32_t)lo[3] << 16);
        lp.z = (uint32_t)lo[4] | ((uint32_t)lo[5] << 16);
        lp.w = (uint32_t)lo[6] | ((uint32_t)lo[7] << 16);
        *(uint4*)((char*)d_Gh + (size_t)row * 512 + lane * 16) = hp;
        *(uint4*)((char*)d_Gl + (size_t)row * 512 + lane * 16) = lp;
    }
}

// ---------------- readout ----------------
__global__ void pool_kernel(const int* __restrict__ batch) {
    __shared__ int sbm[2];
    int b = blockIdx.x, c = threadIdx.x;
    if (c < 2) {
        int target = b + c;
        int lo = 0, hi = Nn;
        while (lo < hi) {
            int mid = (lo + hi) >> 1;
            if (batch[mid] < target) lo = mid + 1; else hi = mid;
        }
        sbm[c] = lo;
    }
    __syncthreads();
    int n0 = sbm[0], n1 = sbm[1];
    float mn = INFINITY, mx = -INFINITY, sm = 0.f;
    for (int n = n0; n < n1; n++) {
        float v = d_OUTf[(size_t)n * HD + c];
        mn = fminf(mn, v); mx = fmaxf(mx, v); sm += v;
    }
    int cnt = n1 - n0;
    if (cnt == 0) { mn = 0.f; mx = 0.f; }
    float mean = sm / fmaxf((float)cnt, 1.f);
    d_G[b * 1024 + c]       = mn;
    d_G[b * 1024 + 256 + c] = mx;
    d_G[b * 1024 + 512 + c] = mean;
    d_G[b * 1024 + 768 + c] = sm;
}

__global__ void head_kernel(const float* __restrict__ hW,
                            const float* __restrict__ hb,
                            float* __restrict__ out) {
    __shared__ float sg[1024];
    int b = blockIdx.x, j = threadIdx.x;
    for (int k = j; k < 1024; k += 128) sg[k] = gelu_f(d_G[b * 1024 + k]);
    __syncthreads();
    float acc = hb[j];
    for (int k = 0; k < 1024; k++) acc += sg[k] * hW[k * NOUT + j];
    out[b * NOUT + j] = acc;
}

// ---------------- launch ----------------
extern "C" void kernel_launch(void* const* d_in, const int* in_sizes, int n_in,
                              void* d_out, int out_size) {
    const float* x      = (const float*)d_in[0];
    const int*   ei     = (const int*)  d_in[1];
    const int*   batch  = (const int*)  d_in[2];
    const float* W0     = (const float*)d_in[3];
    const float* a_src0 = (const float*)d_in[4];
    const float* a_dst0 = (const float*)d_in[5];
    const float* b0     = (const float*)d_in[6];
    const float* Ws     = (const float*)d_in[7];
    const float* a_srcs = (const float*)d_in[8];
    const float* a_dsts = (const float*)d_in[9];
    const float* bs     = (const float*)d_in[10];
    const float* hW     = (const float*)d_in[11];
    const float* hb     = (const float*)d_in[12];
    float* out = (float*)d_out;

    const int* srcp = ei;
    const int* dstp = ei + Ee;

    __nv_bfloat16* pWsw = nullptr;
    cudaGetSymbolAddress((void**)&pWsw, d_Wsw);

    cudaFuncSetAttribute(gat_gemm_kernel,
                         cudaFuncAttributeMaxDynamicSharedMemorySize, GEMM_SMEM);

    deg_init_kernel<<<(Nn + 255) / 256, 256>>>();
    hist_kernel<<<(Ee + 255) / 256, 256>>>(dstp);
    scan_kernel<<<1, 1024>>>();
    scatter_kernel<<<(ET + 255) / 256, 256>>>(srcp, dstp);
    sort_rows_kernel<<<(Nn * 32 + 255) / 256, 256>>>();
    wsplit_kernel<<<(9 * 65536 + 255) / 256, 256>>>(Ws);

    // layer 0 (GEMM K=8 + alpha fused)
    layer0_kernel<<<Nn / 8, 256>>>(x, W0, a_src0, a_dst0);
    agg_kernel<false><<<(Nn * 32 + 255) / 256, 256>>>(b0);

    // layers 1..9
    for (int l = 1; l < NL; l++) {
        gat_gemm_kernel<<<NnP / 128, 256, GEMM_SMEM>>>(
            pWsw + (size_t)(l - 1) * 131072,
            a_srcs + (size_t)(l - 1) * HD, a_dsts + (size_t)(l - 1) * HD);
        if (l < NL - 1)
            agg_kernel<false><<<(Nn * 32 + 255) / 256, 256>>>(
                bs + (size_t)(l - 1) * HD);
        else
            agg_kernel<true><<<(Nn * 32 + 255) / 256, 256>>>(
                bs + (size_t)(l - 1) * HD);
    }

    pool_kernel<<<Bb, 256>>>(batch);
    head_kernel<<<Bb, NOUT>>>(hW, hb, out);
}

// round 5
// speedup vs baseline: 1.7572x; 1.0664x over previous
#include <cuda_runtime.h>
#include <cuda_bf16.h>
#include <math.h>
#include <stdint.h>

#define Nn   30000
#define NnP  30080     // padded to 235*128 for GEMM tiles
#define Ee   480000
#define ET   510000    // Ee + Nn self loops
#define Bb   48
#define HD   256       // H*D
#define NOUT 128
#define NL   10

// ---------------- device scratch (static, no allocs) ----------------
__device__ float4 d_H4[Nn * 64];       // H = gelu(prev) @ W   [N,256] fp32
__device__ float4 d_OUT4[Nn * 64];     // final layer output (pool input)
__device__ float4 d_AS4[Nn];           // alpha_src [N,4]
__device__ float4 d_AD4[Nn];           // alpha_dst [N,4]
__device__ int    d_deg[Nn];
__device__ int    d_rowptr[Nn + 1];
__device__ int    d_cursor[Nn];
__device__ int    d_colsrc[ET];
// gelu(agg out) bf16 split, GEMM A input: [NnP][256]
__device__ __nv_bfloat16 d_Gh[NnP * 256];
__device__ __nv_bfloat16 d_Gl[NnP * 256];
// W split+transposed: [9 layers][hi|lo][n=256][k=256] bf16
__device__ __nv_bfloat16 d_Wsw[9 * 2 * 256 * 256];

#define d_Hf   ((float*)d_H4)
#define d_OUTf ((float*)d_OUT4)
#define d_ASf  ((float*)d_AS4)
#define d_ADf  ((float*)d_AD4)

__device__ __forceinline__ float gelu_f(float x) {
    return 0.5f * x * (1.0f + erff(x * 0.70710678118654752f));
}
__device__ __forceinline__ uint32_t smem_u32(const void* p) {
    uint32_t a;
    asm("{ .reg .u64 t; cvta.to.shared.u64 t, %1; cvt.u32.u64 %0, t; }"
        : "=r"(a) : "l"(p));
    return a;
}
__device__ __forceinline__ void ldsm4(uint32_t* r, uint32_t addr) {
    asm volatile("ldmatrix.sync.aligned.m8n8.x4.shared.b16 {%0,%1,%2,%3}, [%4];"
                 : "=r"(r[0]), "=r"(r[1]), "=r"(r[2]), "=r"(r[3]) : "r"(addr));
}
__device__ __forceinline__ void mma16816(float* c, const uint32_t* a,
                                         const uint32_t* b) {
    asm volatile(
        "mma.sync.aligned.m16n8k16.row.col.f32.bf16.bf16.f32 "
        "{%0,%1,%2,%3}, {%4,%5,%6,%7}, {%8,%9}, {%0,%1,%2,%3};"
        : "+f"(c[0]), "+f"(c[1]), "+f"(c[2]), "+f"(c[3])
        : "r"(a[0]), "r"(a[1]), "r"(a[2]), "r"(a[3]), "r"(b[0]), "r"(b[1]));
}
__device__ __forceinline__ void cp16(uint32_t saddr, const void* gaddr) {
    asm volatile("cp.async.cg.shared.global [%0], [%1], 16;"
                 :: "r"(saddr), "l"(gaddr));
}
#define CP_COMMIT() asm volatile("cp.async.commit_group;" ::: "memory")
#define CP_WAIT1()  asm volatile("cp.async.wait_group 1;" ::: "memory")
#define CP_WAIT0()  asm volatile("cp.async.wait_group 0;" ::: "memory")

// ---------------- CSR build ----------------
__global__ void deg_init_kernel() {
    int i = blockIdx.x * blockDim.x + threadIdx.x;
    if (i < Nn) d_deg[i] = 1;
}
__global__ void hist_kernel(const int* __restrict__ dst) {
    int i = blockIdx.x * blockDim.x + threadIdx.x;
    if (i < Ee) atomicAdd(&d_deg[dst[i]], 1);
}
__global__ void scan_kernel() {
    __shared__ int sh[1024];
    const int t = threadIdx.x;
    const int CH = (Nn + 1023) / 1024;
    int start = t * CH, end = min(start + CH, Nn);
    int s = 0;
    for (int i = start; i < end; i++) s += d_deg[i];
    sh[t] = s;
    __syncthreads();
    for (int off = 1; off < 1024; off <<= 1) {
        int v = (t >= off) ? sh[t - off] : 0;
        __syncthreads();
        sh[t] += v;
        __syncthreads();
    }
    int run = sh[t] - s;
    for (int i = start; i < end; i++) {
        d_rowptr[i] = run; d_cursor[i] = run; run += d_deg[i];
    }
    if (t == 1023) d_rowptr[Nn] = sh[1023];
}
__global__ void scatter_kernel(const int* __restrict__ src,
                               const int* __restrict__ dst) {
    int i = blockIdx.x * blockDim.x + threadIdx.x;
    if (i >= ET) return;
    int s, d;
    if (i < Ee) { s = src[i]; d = dst[i]; }
    else        { s = d = i - Ee; }
    int pos = atomicAdd(&d_cursor[d], 1);
    d_colsrc[pos] = s;
}

// ---------------- fused prologue: sort rows | layer0+alpha | wsplit --------------
// grid = 3750 (sort) + 3750 (layer0) + 2304 (wsplit) blocks, 256 threads each
#define SORT_BLKS  3750
#define L0_BLKS    3750
#define WSP_BLKS   2304

__global__ void fused_pre_kernel(const float* __restrict__ Ws,
                                 const float* __restrict__ x,
                                 const float* __restrict__ W0,
                                 const float* __restrict__ a_src,
                                 const float* __restrict__ a_dst) {
    __shared__ float w[8 * 256];
    __shared__ float sa[256], sd[256];
    const int b = blockIdx.x;
    const int t = threadIdx.x;

    if (b < SORT_BLKS) {
        // odd-even sort of each CSR row (warp/row) for determinism
        int wid = b * 8 + (t >> 5), lane = t & 31;
        if (wid >= Nn) return;
        int s0 = d_rowptr[wid], s1 = d_rowptr[wid + 1];
        int n = s1 - s0;
        for (int p = 0; p < n; p++) {
            for (int i = (p & 1) + 2 * lane; i + 1 < n; i += 64) {
                int a = d_colsrc[s0 + i], bb = d_colsrc[s0 + i + 1];
                if (a > bb) { d_colsrc[s0 + i] = bb; d_colsrc[s0 + i + 1] = a; }
            }
            __syncwarp();
        }
    } else if (b < SORT_BLKS + L0_BLKS) {
        // layer0: H0 = x @ W0 with fused alpha dots (warp/row)
        const int bb = b - SORT_BLKS;
        for (int i = t; i < 2048; i += 256) w[i] = W0[i];
        sa[t] = a_src[t];
        sd[t] = a_dst[t];
        __syncthreads();
        int lane = t & 31;
        int row = bb * 8 + (t >> 5);
        float xr[8];
#pragma unroll
        for (int k = 0; k < 8; k++) xr[k] = __ldg(x + row * 8 + k);
        float ps[4] = {0.f, 0.f, 0.f, 0.f}, pd[4] = {0.f, 0.f, 0.f, 0.f};
        float* op = d_Hf + (size_t)row * HD;
#pragma unroll
        for (int j = 0; j < 8; j++) {
            int col = lane + 32 * j;
            float acc = 0.f;
#pragma unroll
            for (int k = 0; k < 8; k++) acc += xr[k] * w[k * 256 + col];
            op[col] = acc;
            ps[j >> 1] += acc * sa[col];
            pd[j >> 1] += acc * sd[col];
        }
#pragma unroll
        for (int h = 0; h < 4; h++) {
#pragma unroll
            for (int off = 16; off; off >>= 1) {
                ps[h] += __shfl_xor_sync(0xffffffffu, ps[h], off);
                pd[h] += __shfl_xor_sync(0xffffffffu, pd[h], off);
            }
        }
        if (lane < 4) {
            d_ASf[row * 4 + lane] = ps[lane];
            d_ADf[row * 4 + lane] = pd[lane];
        }
    } else {
        // wsplit: [l][hi|lo][n][k] bf16 split+transpose
        int idx = (b - SORT_BLKS - L0_BLKS) * 256 + t;
        if (idx >= 9 * 65536) return;
        int l = idx >> 16;
        int rem = idx & 65535;
        int k = rem >> 8, n = rem & 255;
        float wv = Ws[idx];
        __nv_bfloat16 hi = __float2bfloat16(wv);
        __nv_bfloat16 lo = __float2bfloat16(wv - __bfloat162float(hi));
        __nv_bfloat16* base = d_Wsw + (size_t)l * 131072;
        base[n * 256 + k] = hi;
        base[65536 + n * 256 + k] = lo;
    }
}

// ---------------- HMMA GEMM (layers 1..9): H = (Gh+Gl) @ (Wh+Wl), fused alpha ----------
#define SM_SA    0
#define SM_SD    1024
#define SM_BUF   2048
#define SM_BSTR  61440
#define GEMM_SMEM (2048 + 2 * 61440)

__global__ void __launch_bounds__(256, 1)
gat_gemm_kernel(const __nv_bfloat16* __restrict__ Wsw,
                const float* __restrict__ a_src,
                const float* __restrict__ a_dst) {
    extern __shared__ char smem[];
    const uint32_t sb = smem_u32(smem);
    const int tid = threadIdx.x;
    const int lane = tid & 31;
    const int wid = tid >> 5;
    const int WM = wid >> 2, WN = wid & 3;
    const int row0 = blockIdx.x * 128;

    float* sa = (float*)(smem + SM_SA);
    float* sd = (float*)(smem + SM_SD);
    sa[tid] = a_src[tid];
    sd[tid] = a_dst[tid];

    const char* Wb = (const char*)Wsw;
    const char* Ah = (const char*)d_Gh;
    const char* Al = (const char*)d_Gl;

#define PREFETCH(cc) do {                                                     \
    const int _pb = (cc) & 1;                                                 \
    const uint32_t _bs = sb + SM_BUF + _pb * SM_BSTR;                         \
    _Pragma("unroll")                                                         \
    for (int j = 0; j < 4; j++) {                                             \
        int half = j >> 1;                                                    \
        int idx = tid + (j & 1) * 256;                                        \
        int row = idx >> 2, sg = idx & 3;                                     \
        uint32_t dst = _bs + half * 10240 + row * 80 + sg * 16;               \
        const char* srcb = half ? Al : Ah;                                    \
        cp16(dst, srcb + (size_t)(row0 + row) * 512 + (cc) * 64 + sg * 16);   \
    }                                                                         \
    _Pragma("unroll")                                                         \
    for (int j = 0; j < 8; j++) {                                             \
        int half = j >> 2;                                                    \
        int idx = tid + (j & 3) * 256;                                        \
        int n = idx >> 2, sg = idx & 3;                                       \
        uint32_t dst = _bs + 20480 + half * 20480 + n * 80 + sg * 16;         \
        cp16(dst, Wb + half * 131072 + n * 512 + (cc) * 64 + sg * 16);        \
    }                                                                         \
    CP_COMMIT();                                                              \
} while (0)

    PREFETCH(0);

    float c[4][8][4];
#pragma unroll
    for (int mi = 0; mi < 4; mi++)
#pragma unroll
        for (int ni = 0; ni < 8; ni++)
#pragma unroll
            for (int q = 0; q < 4; q++) c[mi][ni][q] = 0.f;

    const uint32_t aoff = (uint32_t)((WM * 64 + (lane & 15)) * 80 +
                                     (lane >> 4) * 16);
    const uint32_t boff = (uint32_t)((WN * 64 + ((lane >> 4) & 1) * 8 +
                                      (lane & 7)) * 80 +
                                     ((lane >> 3) & 1) * 16);

    for (int cc = 0; cc < 8; cc++) {
        const int buf = cc & 1;
        __syncthreads();
        if (cc < 7) { PREFETCH(cc + 1); CP_WAIT1(); }
        else        { CP_WAIT0(); }
        __syncthreads();

        const uint32_t bs = sb + SM_BUF + buf * SM_BSTR;
        const uint32_t aH = bs, aL = bs + 10240;
        const uint32_t bH = bs + 20480, bL = bs + 40960;
#pragma unroll
        for (int s = 0; s < 2; s++) {
            const uint32_t so = (uint32_t)(s * 32);
            uint32_t ah[4][4], bh[4][4];
#pragma unroll
            for (int mi = 0; mi < 4; mi++)
                ldsm4(ah[mi], aH + aoff + mi * 1280 + so);
#pragma unroll
            for (int p = 0; p < 4; p++)
                ldsm4(bh[p], bH + boff + p * 1280 + so);
#pragma unroll
            for (int mi = 0; mi < 4; mi++)
#pragma unroll
                for (int ni = 0; ni < 8; ni++)
                    mma16816(c[mi][ni], ah[mi], &bh[ni >> 1][(ni & 1) * 2]);
            uint32_t bl[4][4];
#pragma unroll
            for (int p = 0; p < 4; p++)
                ldsm4(bl[p], bL + boff + p * 1280 + so);
#pragma unroll
            for (int mi = 0; mi < 4; mi++)
#pragma unroll
                for (int ni = 0; ni < 8; ni++)
                    mma16816(c[mi][ni], ah[mi], &bl[ni >> 1][(ni & 1) * 2]);
            uint32_t al[4][4];
#pragma unroll
            for (int mi = 0; mi < 4; mi++)
                ldsm4(al[mi], aL + aoff + mi * 1280 + so);
#pragma unroll
            for (int mi = 0; mi < 4; mi++)
#pragma unroll
                for (int ni = 0; ni < 8; ni++)
                    mma16816(c[mi][ni], al[mi], &bh[ni >> 1][(ni & 1) * 2]);
        }
    }
#undef PREFETCH

    // ---- epilogue: fused alpha dots + H writeback ----
    const int colq = WN * 64 + (lane & 3) * 2;
#pragma unroll
    for (int mi = 0; mi < 4; mi++) {
#pragma unroll
        for (int h = 0; h < 2; h++) {
            float ps = 0.f, pd = 0.f;
#pragma unroll
            for (int ni = 0; ni < 8; ni++) {
                float v0 = c[mi][ni][h * 2], v1 = c[mi][ni][h * 2 + 1];
                int col = colq + ni * 8;
                ps += v0 * sa[col] + v1 * sa[col + 1];
                pd += v0 * sd[col] + v1 * sd[col + 1];
            }
            ps += __shfl_xor_sync(0xffffffffu, ps, 1);
            ps += __shfl_xor_sync(0xffffffffu, ps, 2);
            pd += __shfl_xor_sync(0xffffffffu, pd, 1);
            pd += __shfl_xor_sync(0xffffffffu, pd, 2);
            int row = row0 + WM * 64 + mi * 16 + h * 8 + (lane >> 2);
            if ((lane & 3) == 0 && row < Nn) {
                d_ASf[row * 4 + WN] = ps;
                d_ADf[row * 4 + WN] = pd;
            }
        }
    }
#pragma unroll
    for (int mi = 0; mi < 4; mi++) {
#pragma unroll
        for (int h = 0; h < 2; h++) {
            int row = row0 + WM * 64 + mi * 16 + h * 8 + (lane >> 2);
            if (row >= Nn) continue;
            float* op = d_Hf + (size_t)row * HD;
#pragma unroll
            for (int ni = 0; ni < 8; ni++) {
                float2 v = make_float2(c[mi][ni][h * 2], c[mi][ni][h * 2 + 1]);
                *(float2*)(op + colq + ni * 8) = v;
            }
        }
    }
}

// ------ aggregation: ONE pass, post-normalized softmax, pipelined edge loop ------
template <bool LAST>
__global__ void agg_kernel(const float* __restrict__ bias) {
    int t = blockIdx.x * blockDim.x + threadIdx.x;
    int row = t >> 5, lane = t & 31;
    if (row >= Nn) return;
    const int hh = lane >> 3;
    const int s0 = d_rowptr[row], s1 = d_rowptr[row + 1];

    float4 adv = d_AD4[row];
    const float ad = (hh == 0) ? adv.x : (hh == 1) ? adv.y
                   : (hh == 2) ? adv.z : adv.w;

    float z = 0.f;
    float4 acc0 = make_float4(0.f, 0.f, 0.f, 0.f);
    float4 acc1 = make_float4(0.f, 0.f, 0.f, 0.f);

    // degree >= 1 always (self loop). Prefetch next colsrc to break the
    // colsrc -> (AS, H) dependent chain.
    int nsrc = __ldg(d_colsrc + s0);
    for (int e = s0; e < s1; e++) {
        const int scur = nsrc;
        if (e + 1 < s1) nsrc = __ldg(d_colsrc + e + 1);
        float4 asv = __ldg(d_AS4 + scur);
        float a = (hh == 0) ? asv.x : (hh == 1) ? asv.y
                : (hh == 2) ? asv.z : asv.w;
        float tt = a + ad;
        tt = tt > 0.f ? tt : 0.2f * tt;
        float wgt = expf(tt);
        z += wgt;
        const float4* hp = d_H4 + (size_t)scur * 64 + lane * 2;
        float4 v0 = hp[0], v1 = hp[1];
        acc0.x += wgt * v0.x; acc0.y += wgt * v0.y;
        acc0.z += wgt * v0.z; acc0.w += wgt * v0.w;
        acc1.x += wgt * v1.x; acc1.y += wgt * v1.y;
        acc1.z += wgt * v1.z; acc1.w += wgt * v1.w;
    }
    // z is identical across the 8 lanes of a head (same serial sum) — no shuffle
    const float invz = 1.f / (z + 1e-16f);

    const float4* bp = (const float4*)(bias + lane * 8);
    float4 b0 = bp[0], b1 = bp[1];
    acc0.x = acc0.x * invz + b0.x; acc0.y = acc0.y * invz + b0.y;
    acc0.z = acc0.z * invz + b0.z; acc0.w = acc0.w * invz + b0.w;
    acc1.x = acc1.x * invz + b1.x; acc1.y = acc1.y * invz + b1.y;
    acc1.z = acc1.z * invz + b1.z; acc1.w = acc1.w * invz + b1.w;

    if (LAST) {
        float* op = d_OUTf + (size_t)row * HD + lane * 8;
        *(float4*)op = acc0;
        *(float4*)(op + 4) = acc1;
    } else {
        float g[8] = {acc0.x, acc0.y, acc0.z, acc0.w,
                      acc1.x, acc1.y, acc1.z, acc1.w};
        uint16_t hi[8], lo[8];
#pragma unroll
        for (int q = 0; q < 8; q++) {
            float gv = gelu_f(g[q]);
            __nv_bfloat16 h = __float2bfloat16(gv);
            hi[q] = __bfloat16_as_ushort(h);
            lo[q] = __bfloat16_as_ushort(
                __float2bfloat16(gv - __bfloat162float(h)));
        }
        uint4 hp, lp;
        hp.x = (uint32_t)hi[0] | ((uint32_t)hi[1] << 16);
        hp.y = (uint32_t)hi[2] | ((uint32_t)hi[3] << 16);
        hp.z = (uint32_t)hi[4] | ((uint32_t)hi[5] << 16);
        hp.w = (uint32_t)hi[6] | ((uint32_t)hi[7] << 16);
        lp.x = (uint32_t)lo[0] | ((uint32_t)lo[1] << 16);
        lp.y = (uint32_t)lo[2] | ((uint32_t)lo[3] << 16);
        lp.z = (uint32_t)lo[4] | ((uint32_t)lo[5] << 16);
        lp.w = (uint32_t)lo[6] | ((uint32_t)lo[7] << 16);
        *(uint4*)((char*)d_Gh + (size_t)row * 512 + lane * 16) = hp;
        *(uint4*)((char*)d_Gl + (size_t)row * 512 + lane * 16) = lp;
    }
}

// ---------------- fused readout: pool [min|max|mean|sum] -> gelu -> head ------
__global__ void readout_kernel(const int* __restrict__ batch,
                               const float* __restrict__ hW,
                               const float* __restrict__ hb,
                               float* __restrict__ out) {
    __shared__ float sg[1024];
    __shared__ int sbm[2];
    int b = blockIdx.x, c = threadIdx.x;   // 256 threads
    if (c < 2) {
        int target = b + c;
        int lo = 0, hi = Nn;
        while (lo < hi) {
            int mid = (lo + hi) >> 1;
            if (batch[mid] < target) lo = mid + 1; else hi = mid;
        }
        sbm[c] = lo;
    }
    __syncthreads();
    int n0 = sbm[0], n1 = sbm[1];
    float mn = INFINITY, mx = -INFINITY, sm = 0.f;
    for (int n = n0; n < n1; n++) {
        float v = d_OUTf[(size_t)n * HD + c];
        mn = fminf(mn, v); mx = fmaxf(mx, v); sm += v;
    }
    int cnt = n1 - n0;
    if (cnt == 0) { mn = 0.f; mx = 0.f; }
    float mean = sm / fmaxf((float)cnt, 1.f);
    sg[c]       = gelu_f(mn);
    sg[256 + c] = gelu_f(mx);
    sg[512 + c] = gelu_f(mean);
    sg[768 + c] = gelu_f(sm);
    __syncthreads();
    if (c < NOUT) {
        float acc = hb[c];
        for (int k = 0; k < 1024; k++) acc += sg[k] * hW[k * NOUT + c];
        out[b * NOUT + c] = acc;
    }
}

// ---------------- launch ----------------
extern "C" void kernel_launch(void* const* d_in, const int* in_sizes, int n_in,
                              void* d_out, int out_size) {
    const float* x      = (const float*)d_in[0];
    const int*   ei     = (const int*)  d_in[1];
    const int*   batch  = (const int*)  d_in[2];
    const float* W0     = (const float*)d_in[3];
    const float* a_src0 = (const float*)d_in[4];
    const float* a_dst0 = (const float*)d_in[5];
    const float* b0     = (const float*)d_in[6];
    const float* Ws     = (const float*)d_in[7];
    const float* a_srcs = (const float*)d_in[8];
    const float* a_dsts = (const float*)d_in[9];
    const float* bs     = (const float*)d_in[10];
    const float* hW     = (const float*)d_in[11];
    const float* hb     = (const float*)d_in[12];
    float* out = (float*)d_out;

    const int* srcp = ei;
    const int* dstp = ei + Ee;

    __nv_bfloat16* pWsw = nullptr;
    cudaGetSymbolAddress((void**)&pWsw, d_Wsw);

    cudaFuncSetAttribute(gat_gemm_kernel,
                         cudaFuncAttributeMaxDynamicSharedMemorySize, GEMM_SMEM);

    deg_init_kernel<<<(Nn + 255) / 256, 256>>>();                    // 0
    hist_kernel<<<(Ee + 255) / 256, 256>>>(dstp);                    // 1
    scan_kernel<<<1, 1024>>>();                                      // 2
    scatter_kernel<<<(ET + 255) / 256, 256>>>(srcp, dstp);           // 3
    fused_pre_kernel<<<SORT_BLKS + L0_BLKS + WSP_BLKS, 256>>>(       // 4
        Ws, x, W0, a_src0, a_dst0);

    agg_kernel<false><<<(Nn * 32 + 255) / 256, 256>>>(b0);           // 5 (ncu)

    for (int l = 1; l < NL; l++) {
        gat_gemm_kernel<<<NnP / 128, 256, GEMM_SMEM>>>(
            pWsw + (size_t)(l - 1) * 131072,
            a_srcs + (size_t)(l - 1) * HD, a_dsts + (size_t)(l - 1) * HD);
        if (l < NL - 1)
            agg_kernel<false><<<(Nn * 32 + 255) / 256, 256>>>(
                bs + (size_t)(l - 1) * HD);
        else
            agg_kernel<true><<<(Nn * 32 + 255) / 256, 256>>>(
                bs + (size_t)(l - 1) * HD);
    }

    readout_kernel<<<Bb, 256>>>(batch, hW, hb, out);
}